// round 13
// baseline (speedup 1.0000x reference)
#include <cuda_runtime.h>
#include <cuda_bf16.h>
#include <cstdint>

#define INDIM 128
#define HIDC  256
#define NBAT  4096
#define N2C   12288
#define FANC  10
#define N1C   122880
#define NT0   (N1C / 64)   // 1920 layer0 tiles

// ---------------- scratch ----------------
__device__ float    g_h0[(size_t)N1C * HIDC];
__device__ float    g_h2[(size_t)N2C * HIDC];
__device__ uint32_t g_W0hi[128 * 256];   // stacked [Ws0;Wn0], 128 pk rows
__device__ uint32_t g_W0lo[128 * 256];
__device__ uint32_t g_W1hi[256 * 256];   // stacked [Ws1;Wn1], 256 pk rows
__device__ uint32_t g_W1lo[256 * 256];
__device__ uint32_t g_P1hi[128 * 256];
__device__ uint32_t g_P1lo[128 * 256];
__device__ uint32_t g_P2hi[128 * 256];
__device__ uint32_t g_P2lo[128 * 256];

// ---------------- bf16 split helpers ----------------
__device__ __forceinline__ void split_pack(float a, float b, uint32_t& hi, uint32_t& lo) {
    __nv_bfloat16 ha = __float2bfloat16_rn(a);
    __nv_bfloat16 hb = __float2bfloat16_rn(b);
    float la = a - __bfloat162float(ha);
    float lb = b - __bfloat162float(hb);
    __nv_bfloat16 sa = __float2bfloat16_rn(la);
    __nv_bfloat16 sb = __float2bfloat16_rn(lb);
    hi = ((uint32_t)__bfloat16_as_ushort(hb) << 16) | (uint32_t)__bfloat16_as_ushort(ha);
    lo = ((uint32_t)__bfloat16_as_ushort(sb) << 16) | (uint32_t)__bfloat16_as_ushort(sa);
}

__device__ __forceinline__ void store_split4(uint32_t* Ahi, uint32_t* Alo, int idx, float4 v) {
    uint32_t h0, l0, h1, l1;
    split_pack(v.x, v.y, h0, l0);
    split_pack(v.z, v.w, h1, l1);
    *(uint2*)&Ahi[idx] = make_uint2(h0, h1);
    *(uint2*)&Alo[idx] = make_uint2(l0, l1);
}

#define MMA_BF16(c, a, b0v, b1v) \
    asm volatile("mma.sync.aligned.m16n8k16.row.col.f32.bf16.bf16.f32 " \
        "{%0,%1,%2,%3}, {%4,%5,%6,%7}, {%8,%9}, {%0,%1,%2,%3};" \
        : "+f"((c)[0]), "+f"((c)[1]), "+f"((c)[2]), "+f"((c)[3]) \
        : "r"((a)[0]), "r"((a)[1]), "r"((a)[2]), "r"((a)[3]), "r"(b0v), "r"(b1v))

#define NB_SYNC(id, cnt)   asm volatile("bar.sync %0, %1;"   :: "r"(id), "r"(cnt) : "memory")
#define NB_ARRIVE(id, cnt) asm volatile("bar.arrive %0, %1;" :: "r"(id), "r"(cnt) : "memory")

// ---------------- single merged weight pre-split ----------------
__global__ void __launch_bounds__(256)
prep_all(const float* __restrict__ Ws0, const float* __restrict__ Wn0,
         const float* __restrict__ Ws1, const float* __restrict__ Wn1,
         const float* __restrict__ Wp1, const float* __restrict__ Wp2,
         uint32_t* __restrict__ W0hi, uint32_t* __restrict__ W0lo,
         uint32_t* __restrict__ W1hi, uint32_t* __restrict__ W1lo,
         uint32_t* __restrict__ P1hi, uint32_t* __restrict__ P1lo,
         uint32_t* __restrict__ P2hi, uint32_t* __restrict__ P2lo)
{
    int b = blockIdx.x, n = threadIdx.x;
    const float *Wa, *Wb;
    uint32_t *Whi, *Wlo;
    int pk, Ka;
    if (b < 128)      { Wa = Ws0; Wb = Wn0; Whi = W0hi; Wlo = W0lo; pk = b;       Ka = 128; }
    else if (b < 384) { Wa = Ws1; Wb = Wn1; Whi = W1hi; Wlo = W1lo; pk = b - 128; Ka = 256; }
    else if (b < 512) { Wa = Wp1; Wb = Wp1; Whi = P1hi; Wlo = P1lo; pk = b - 384; Ka = 256; }
    else              { Wa = Wp2; Wb = Wp2; Whi = P2hi; Wlo = P2lo; pk = b - 512; Ka = 256; }
    int k0 = 2 * pk, k1 = 2 * pk + 1;
    float f0 = (k0 < Ka) ? __ldg(&Wa[(size_t)k0 * 256 + n]) : __ldg(&Wb[(size_t)(k0 - Ka) * 256 + n]);
    float f1 = (k1 < Ka) ? __ldg(&Wa[(size_t)k1 * 256 + n]) : __ldg(&Wb[(size_t)(k1 - Ka) * 256 + n]);
    uint32_t h, l;
    split_pack(f0, f1, h, l);
    Whi[(size_t)pk * 256 + n] = h;
    Wlo[(size_t)pk * 256 + n] = l;
}

// ---------------- layer0: persistent warp-specialized gather + GEMM ----------------
// 512 threads: warps 0-7 produce split A tiles (BM=64, double-buffered),
// warps 8-15 stage B (pre-split) + MMA + epilogue. Named-barrier handoff.
__global__ void __launch_bounds__(512, 1)
l0_ws(const float* __restrict__ src,
      const int*   __restrict__ gids,
      const int*   __restrict__ neigh,
      const uint32_t* __restrict__ Whi,
      const uint32_t* __restrict__ Wlo,
      const float* __restrict__ bias,
      float*       __restrict__ out)
{
    constexpr int LDA_U = 132;          // 128 pk + 4 pad
    constexpr int A_U   = 64 * LDA_U;   // one buffer (per hi/lo)
    constexpr int LDB_U = 264;
    constexpr int B_U   = 16 * LDB_U;

    extern __shared__ uint32_t smem[];
    uint32_t* AhB = smem;               // [2][A_U]
    uint32_t* AlB = smem + 2 * A_U;     // [2][A_U]
    uint32_t* Bh  = smem + 4 * A_U;
    uint32_t* Bl  = Bh + B_U;
    float*    bsm = (float*)(Bl + B_U);
    int*      sidxB = (int*)(bsm + 256);   // [2][64]
    int*      nidxB = sidxB + 128;         // [2][640]

    const int tid  = threadIdx.x;
    const int lane = tid & 31;
    const int wid  = tid >> 5;
    const bool producer = (wid < 8);
    const float4* src4 = (const float4*)src;

    if (tid < 256) bsm[tid] = bias[tid];
    __syncthreads();

    int it = 0;
    for (int t = blockIdx.x; t < NT0; t += gridDim.x, it++) {
        const int b = it & 1;

        if (producer) {
            if (it >= 2) NB_SYNC(3 + b, 512);   // wait buffer empty

            // resolve indices (256 producer threads)
            int* sx = sidxB + b * 64;
            int* nx = nidxB + b * 640;
            if (tid < 64) sx[tid] = __ldg(&gids[t * 64 + tid]);
            for (int e = tid; e < 640; e += 256) {
                int nj = __ldg(&neigh[(size_t)t * 640 + e]);
                nx[e] = __ldg(&gids[nj]);
            }
            NB_SYNC(6, 256);                    // indices ready (producer-internal)

            uint32_t* AH = AhB + b * A_U;
            uint32_t* AL = AlB + b * A_U;
            #pragma unroll 1
            for (int g = 0; g < 4; g++) {
                const int r0 = wid + 8 * (2 * g);
                const int r1 = wid + 8 * (2 * g + 1);
                float4 s0 = __ldg(&src4[(size_t)sx[r0] * 32 + lane]);
                float4 s1 = __ldg(&src4[(size_t)sx[r1] * 32 + lane]);
                float4 t0[FANC], t1[FANC];
                #pragma unroll
                for (int f = 0; f < FANC; f++) t0[f] = __ldg(&src4[(size_t)nx[r0 * FANC + f] * 32 + lane]);
                #pragma unroll
                for (int f = 0; f < FANC; f++) t1[f] = __ldg(&src4[(size_t)nx[r1 * FANC + f] * 32 + lane]);
                float4 a0 = make_float4(0.f, 0.f, 0.f, 0.f);
                float4 a1 = make_float4(0.f, 0.f, 0.f, 0.f);
                #pragma unroll
                for (int f = 0; f < FANC; f++) {
                    a0.x += t0[f].x; a0.y += t0[f].y; a0.z += t0[f].z; a0.w += t0[f].w;
                    a1.x += t1[f].x; a1.y += t1[f].y; a1.z += t1[f].z; a1.w += t1[f].w;
                }
                store_split4(AH, AL, r0 * LDA_U + 2 * lane, s0);
                store_split4(AH, AL, r1 * LDA_U + 2 * lane, s1);
                store_split4(AH, AL, r0 * LDA_U + 64 + 2 * lane,
                             make_float4(a0.x * 0.1f, a0.y * 0.1f, a0.z * 0.1f, a0.w * 0.1f));
                store_split4(AH, AL, r1 * LDA_U + 64 + 2 * lane,
                             make_float4(a1.x * 0.1f, a1.y * 0.1f, a1.z * 0.1f, a1.w * 0.1f));
            }
            __threadfence_block();
            NB_ARRIVE(1 + b, 512);              // buffer full
        } else {
            NB_SYNC(1 + b, 512);                // wait buffer full

            const int ctid = tid - 256;
            const int cw   = wid - 8;
            const int wr   = cw >> 2;           // 0..1
            const int wc   = cw & 3;            // 0..3
            const uint32_t* AH = AhB + b * A_U;
            const uint32_t* AL = AlB + b * A_U;

            float acc[2][8][4];
            #pragma unroll
            for (int mt = 0; mt < 2; mt++)
                #pragma unroll
                for (int nt = 0; nt < 8; nt++)
                    #pragma unroll
                    for (int q = 0; q < 4; q++) acc[mt][nt][q] = 0.f;

            #pragma unroll 1
            for (int c = 0; c < 8; c++) {
                NB_SYNC(5, 256);                // prev chunk MMA done
                {
                    int kp = ctid >> 4, seg = (ctid & 15) * 16;
                    const uint4* gh = (const uint4*)(Whi + (size_t)(c * 16 + kp) * 256 + seg);
                    const uint4* gl = (const uint4*)(Wlo + (size_t)(c * 16 + kp) * 256 + seg);
                    #pragma unroll
                    for (int u = 0; u < 4; u++) {
                        *(uint4*)&Bh[kp * LDB_U + seg + 4 * u] = __ldg(gh + u);
                        *(uint4*)&Bl[kp * LDB_U + seg + 4 * u] = __ldg(gl + u);
                    }
                }
                NB_SYNC(5, 256);                // B chunk ready

                #pragma unroll
                for (int ks = 0; ks < 2; ks++) {
                    const int kpo = c * 16 + ks * 8;
                    uint32_t ah[2][4], al[2][4];
                    const int ab = (wr * 32 + (lane >> 2)) * LDA_U + (lane & 3) + kpo;
                    #pragma unroll
                    for (int mt = 0; mt < 2; mt++) {
                        int a0i = ab + mt * 16 * LDA_U;
                        ah[mt][0] = AH[a0i];
                        ah[mt][1] = AH[a0i + 8 * LDA_U];
                        ah[mt][2] = AH[a0i + 4];
                        ah[mt][3] = AH[a0i + 8 * LDA_U + 4];
                        al[mt][0] = AL[a0i];
                        al[mt][1] = AL[a0i + 8 * LDA_U];
                        al[mt][2] = AL[a0i + 4];
                        al[mt][3] = AL[a0i + 8 * LDA_U + 4];
                    }
                    const int bb = (ks * 8 + (lane & 3)) * LDB_U + wc * 64 + (lane >> 2);
                    #pragma unroll
                    for (int nt = 0; nt < 8; nt++) {
                        int bi = bb + nt * 8;
                        uint32_t bh0 = Bh[bi], bh1 = Bh[bi + 4 * LDB_U];
                        uint32_t bl0 = Bl[bi], bl1 = Bl[bi + 4 * LDB_U];
                        #pragma unroll
                        for (int mt = 0; mt < 2; mt++) {
                            MMA_BF16(acc[mt][nt], ah[mt], bh0, bh1);
                            MMA_BF16(acc[mt][nt], ah[mt], bl0, bl1);
                            MMA_BF16(acc[mt][nt], al[mt], bh0, bh1);
                        }
                    }
                }
            }
            NB_ARRIVE(3 + b, 512);              // buffer empty (A fully consumed)

            // epilogue
            const int row0 = t * 64 + wr * 32 + (lane >> 2);
            #pragma unroll
            for (int mt = 0; mt < 2; mt++) {
                #pragma unroll
                for (int nt = 0; nt < 8; nt++) {
                    int col = wc * 64 + nt * 8 + 2 * (lane & 3);
                    float b0 = bsm[col], b1 = bsm[col + 1];
                    float v0 = fmaxf(acc[mt][nt][0] + b0, 0.f);
                    float v1 = fmaxf(acc[mt][nt][1] + b1, 0.f);
                    float v2 = fmaxf(acc[mt][nt][2] + b0, 0.f);
                    float v3 = fmaxf(acc[mt][nt][3] + b1, 0.f);
                    int r = row0 + mt * 16;
                    *(float2*)&out[(size_t)r * HIDC + col]       = make_float2(v0, v1);
                    *(float2*)&out[(size_t)(r + 8) * HIDC + col] = make_float2(v2, v3);
                }
            }
        }
    }
}

// ---------------- layer1: two-pass fused (BM=64, 256 threads) ----------------
__global__ void __launch_bounds__(256, 2)
l1_gemm(const float* __restrict__ src,
        const int*   __restrict__ neigh,
        const uint32_t* __restrict__ Whi,
        const uint32_t* __restrict__ Wlo,
        const float* __restrict__ bias,
        float*       __restrict__ out)
{
    constexpr int LDA_U = 132;
    constexpr int A_U   = 64 * LDA_U;
    constexpr int LDB_U = 264;
    constexpr int B_U   = 16 * LDB_U;

    extern __shared__ uint32_t smem[];
    uint32_t* Ah = smem;
    uint32_t* Al = Ah + A_U;
    uint32_t* Bh = Al + A_U;
    uint32_t* Bl = Bh + B_U;
    float*    bsm = (float*)(Bl + B_U);
    int*      nidx = (int*)(bsm + 256);

    const int tid  = threadIdx.x;
    const int lane = tid & 31;
    const int wid  = tid >> 5;
    const int wr   = wid >> 2;
    const int wc   = wid & 3;
    const int base = blockIdx.x * 64;
    const float4* src4 = (const float4*)src;

    bsm[tid] = bias[tid];
    for (int e = tid; e < 64 * FANC; e += 256)
        nidx[e] = __ldg(&neigh[(size_t)base * FANC + e]);
    __syncthreads();

    float acc[2][8][4];
    #pragma unroll
    for (int mt = 0; mt < 2; mt++)
        #pragma unroll
        for (int nt = 0; nt < 8; nt++)
            #pragma unroll
            for (int q = 0; q < 4; q++) acc[mt][nt][q] = 0.f;

    #pragma unroll 1
    for (int pass = 0; pass < 2; pass++) {
        if (pass == 0) {
            #pragma unroll
            for (int j = 0; j < 8; j++) {
                int r = wid + 8 * j;
                const float4* p = src4 + (size_t)(base + r) * 64;
                float4 v0 = __ldg(p + lane);
                float4 v1 = __ldg(p + lane + 32);
                store_split4(Ah, Al, r * LDA_U + 2 * lane, v0);
                store_split4(Ah, Al, r * LDA_U + 2 * (lane + 32), v1);
            }
        } else {
            #pragma unroll 1
            for (int j = 0; j < 8; j++) {
                int r = wid + 8 * j;
                float4 t0[FANC], t1[FANC];
                #pragma unroll
                for (int f = 0; f < FANC; f++) {
                    const float4* p = src4 + (size_t)nidx[r * FANC + f] * 64;
                    t0[f] = __ldg(p + lane);
                    t1[f] = __ldg(p + lane + 32);
                }
                float4 a0 = make_float4(0.f, 0.f, 0.f, 0.f);
                float4 a1 = make_float4(0.f, 0.f, 0.f, 0.f);
                #pragma unroll
                for (int f = 0; f < FANC; f++) {
                    a0.x += t0[f].x; a0.y += t0[f].y; a0.z += t0[f].z; a0.w += t0[f].w;
                    a1.x += t1[f].x; a1.y += t1[f].y; a1.z += t1[f].z; a1.w += t1[f].w;
                }
                store_split4(Ah, Al, r * LDA_U + 2 * lane,
                             make_float4(a0.x * 0.1f, a0.y * 0.1f, a0.z * 0.1f, a0.w * 0.1f));
                store_split4(Ah, Al, r * LDA_U + 2 * (lane + 32),
                             make_float4(a1.x * 0.1f, a1.y * 0.1f, a1.z * 0.1f, a1.w * 0.1f));
            }
        }

        #pragma unroll 1
        for (int c = 0; c < 8; c++) {
            {
                int kp = tid >> 4, seg = (tid & 15) * 16;
                const uint4* gh = (const uint4*)(Whi + (size_t)(pass * 128 + c * 16 + kp) * 256 + seg);
                const uint4* gl = (const uint4*)(Wlo + (size_t)(pass * 128 + c * 16 + kp) * 256 + seg);
                #pragma unroll
                for (int u = 0; u < 4; u++) {
                    *(uint4*)&Bh[kp * LDB_U + seg + 4 * u] = __ldg(gh + u);
                    *(uint4*)&Bl[kp * LDB_U + seg + 4 * u] = __ldg(gl + u);
                }
            }
            __syncthreads();

            #pragma unroll
            for (int ks = 0; ks < 2; ks++) {
                const int kpo = c * 16 + ks * 8;
                uint32_t ah[2][4], al[2][4];
                const int ab = (wr * 32 + (lane >> 2)) * LDA_U + (lane & 3) + kpo;
                #pragma unroll
                for (int mt = 0; mt < 2; mt++) {
                    int a0i = ab + mt * 16 * LDA_U;
                    ah[mt][0] = Ah[a0i];
                    ah[mt][1] = Ah[a0i + 8 * LDA_U];
                    ah[mt][2] = Ah[a0i + 4];
                    ah[mt][3] = Ah[a0i + 8 * LDA_U + 4];
                    al[mt][0] = Al[a0i];
                    al[mt][1] = Al[a0i + 8 * LDA_U];
                    al[mt][2] = Al[a0i + 4];
                    al[mt][3] = Al[a0i + 8 * LDA_U + 4];
                }
                const int bb = (ks * 8 + (lane & 3)) * LDB_U + wc * 64 + (lane >> 2);
                #pragma unroll
                for (int nt = 0; nt < 8; nt++) {
                    int bi = bb + nt * 8;
                    uint32_t bh0 = Bh[bi], bh1 = Bh[bi + 4 * LDB_U];
                    uint32_t bl0 = Bl[bi], bl1 = Bl[bi + 4 * LDB_U];
                    #pragma unroll
                    for (int mt = 0; mt < 2; mt++) {
                        MMA_BF16(acc[mt][nt], ah[mt], bh0, bh1);
                        MMA_BF16(acc[mt][nt], ah[mt], bl0, bl1);
                        MMA_BF16(acc[mt][nt], al[mt], bh0, bh1);
                    }
                }
            }
            __syncthreads();
        }
    }

    const int row0 = base + wr * 32 + (lane >> 2);
    #pragma unroll
    for (int mt = 0; mt < 2; mt++) {
        #pragma unroll
        for (int nt = 0; nt < 8; nt++) {
            int col = wc * 64 + nt * 8 + 2 * (lane & 3);
            float b0 = bsm[col], b1 = bsm[col + 1];
            int r = row0 + mt * 16;
            *(float2*)&out[(size_t)r * HIDC + col] =
                make_float2(acc[mt][nt][0] + b0, acc[mt][nt][1] + b1);
            *(float2*)&out[(size_t)(r + 8) * HIDC + col] =
                make_float2(acc[mt][nt][2] + b0, acc[mt][nt][3] + b1);
        }
    }
}

// ---------------- fused MLP1 + MLP2 + score ----------------
__global__ void __launch_bounds__(256, 2)
mlp_fused(const float* __restrict__ h2,
          const uint32_t* __restrict__ P1hi, const uint32_t* __restrict__ P1lo,
          const float* __restrict__ bp1,
          const uint32_t* __restrict__ P2hi, const uint32_t* __restrict__ P2lo,
          const float* __restrict__ bp2,
          const float* __restrict__ Wp3, const float* __restrict__ bp3,
          float* __restrict__ out)
{
    constexpr int LDA_U = 132;
    constexpr int A_U   = 64 * LDA_U;
    constexpr int LDB_U = 264;
    constexpr int B_U   = 16 * LDB_U;

    extern __shared__ uint32_t smem[];
    uint32_t* Ahi = smem;
    uint32_t* Alo = Ahi + A_U;
    uint32_t* Bhi = Alo + A_U;
    uint32_t* Blo = Bhi + B_U;
    float* bsm1 = (float*)(Blo + B_U);
    float* bsm2 = bsm1 + 256;
    float* w3   = bsm2 + 256;
    float* sred = w3 + 256;

    const int tid  = threadIdx.x;
    const int lane = tid & 31;
    const int wid  = tid >> 5;
    const int wr   = wid >> 2;
    const int wc   = wid & 3;
    const float4* src4 = (const float4*)h2;

    bsm1[tid] = bp1[tid];
    bsm2[tid] = bp2[tid];
    w3[tid]   = Wp3[tid];
    if (tid < 64) sred[tid] = bp3[0];

    for (int r = wid; r < 64; r += 8) {
        int i = blockIdx.x * 64 + r;
        const float4* pa = src4 + (size_t)(i & (NBAT - 1)) * 64;
        const float4* pb = src4 + (size_t)(NBAT + i) * 64;
        #pragma unroll
        for (int h = 0; h < 2; h++) {
            float4 x = __ldg(pa + lane + 32 * h);
            float4 y = __ldg(pb + lane + 32 * h);
            store_split4(Ahi, Alo, r * LDA_U + 2 * (lane + 32 * h),
                         make_float4(x.x * y.x, x.y * y.y, x.z * y.z, x.w * y.w));
        }
    }

    float acc[2][8][4];

    #pragma unroll 1
    for (int layer = 0; layer < 2; layer++) {
        const uint32_t* Wh = (layer == 0) ? P1hi : P2hi;
        const uint32_t* Wl = (layer == 0) ? P1lo : P2lo;

        #pragma unroll
        for (int mt = 0; mt < 2; mt++)
            #pragma unroll
            for (int nt = 0; nt < 8; nt++)
                #pragma unroll
                for (int q = 0; q < 4; q++) acc[mt][nt][q] = 0.f;

        #pragma unroll 1
        for (int c = 0; c < 8; c++) {
            {
                int kp = tid >> 4, seg = (tid & 15) * 16;
                const uint4* gh = (const uint4*)(Wh + (size_t)(c * 16 + kp) * 256 + seg);
                const uint4* gl = (const uint4*)(Wl + (size_t)(c * 16 + kp) * 256 + seg);
                #pragma unroll
                for (int u = 0; u < 4; u++) {
                    *(uint4*)&Bhi[kp * LDB_U + seg + 4 * u] = __ldg(gh + u);
                    *(uint4*)&Blo[kp * LDB_U + seg + 4 * u] = __ldg(gl + u);
                }
            }
            __syncthreads();

            #pragma unroll
            for (int ks = 0; ks < 2; ks++) {
                const int kpo = c * 16 + ks * 8;
                uint32_t ah[2][4], al[2][4];
                const int abase = (wr * 32 + (lane >> 2)) * LDA_U + (lane & 3) + kpo;
                #pragma unroll
                for (int mt = 0; mt < 2; mt++) {
                    int a0i = abase + mt * 16 * LDA_U;
                    ah[mt][0] = Ahi[a0i];
                    ah[mt][1] = Ahi[a0i + 8 * LDA_U];
                    ah[mt][2] = Ahi[a0i + 4];
                    ah[mt][3] = Ahi[a0i + 8 * LDA_U + 4];
                    al[mt][0] = Alo[a0i];
                    al[mt][1] = Alo[a0i + 8 * LDA_U];
                    al[mt][2] = Alo[a0i + 4];
                    al[mt][3] = Alo[a0i + 8 * LDA_U + 4];
                }
                const int bbase = (ks * 8 + (lane & 3)) * LDB_U + wc * 64 + (lane >> 2);
                #pragma unroll
                for (int nt = 0; nt < 8; nt++) {
                    int bi = bbase + nt * 8;
                    uint32_t bh0 = Bhi[bi], bh1 = Bhi[bi + 4 * LDB_U];
                    uint32_t bl0 = Blo[bi], bl1 = Blo[bi + 4 * LDB_U];
                    #pragma unroll
                    for (int mt = 0; mt < 2; mt++) {
                        MMA_BF16(acc[mt][nt], ah[mt], bh0, bh1);
                        MMA_BF16(acc[mt][nt], ah[mt], bl0, bl1);
                        MMA_BF16(acc[mt][nt], al[mt], bh0, bh1);
                    }
                }
            }
            __syncthreads();
        }

        if (layer == 0) {
            #pragma unroll
            for (int mt = 0; mt < 2; mt++) {
                int r = wr * 32 + (lane >> 2) + mt * 16;
                #pragma unroll
                for (int nt = 0; nt < 8; nt++) {
                    int col = wc * 64 + nt * 8 + 2 * (lane & 3);
                    float b0 = bsm1[col], b1 = bsm1[col + 1];
                    float v0 = fmaxf(acc[mt][nt][0] + b0, 0.f);
                    float v1 = fmaxf(acc[mt][nt][1] + b1, 0.f);
                    float v2 = fmaxf(acc[mt][nt][2] + b0, 0.f);
                    float v3 = fmaxf(acc[mt][nt][3] + b1, 0.f);
                    uint32_t h, l;
                    split_pack(v0, v1, h, l);
                    Ahi[r * LDA_U + (col >> 1)] = h;
                    Alo[r * LDA_U + (col >> 1)] = l;
                    split_pack(v2, v3, h, l);
                    Ahi[(r + 8) * LDA_U + (col >> 1)] = h;
                    Alo[(r + 8) * LDA_U + (col >> 1)] = l;
                }
            }
            __syncthreads();
        }
    }

    #pragma unroll
    for (int mt = 0; mt < 2; mt++) {
        float sA = 0.f, sB = 0.f;
        #pragma unroll
        for (int nt = 0; nt < 8; nt++) {
            int col = wc * 64 + nt * 8 + 2 * (lane & 3);
            float b0 = bsm2[col], b1 = bsm2[col + 1];
            float w0 = w3[col],  w1 = w3[col + 1];
            sA += fmaxf(acc[mt][nt][0] + b0, 0.f) * w0 + fmaxf(acc[mt][nt][1] + b1, 0.f) * w1;
            sB += fmaxf(acc[mt][nt][2] + b0, 0.f) * w0 + fmaxf(acc[mt][nt][3] + b1, 0.f) * w1;
        }
        sA += __shfl_xor_sync(0xffffffffu, sA, 1);
        sA += __shfl_xor_sync(0xffffffffu, sA, 2);
        sB += __shfl_xor_sync(0xffffffffu, sB, 1);
        sB += __shfl_xor_sync(0xffffffffu, sB, 2);
        if ((lane & 3) == 0) {
            int r = wr * 32 + (lane >> 2) + mt * 16;
            atomicAdd(&sred[r], sA);
            atomicAdd(&sred[r + 8], sB);
        }
    }
    __syncthreads();
    if (tid < 64) out[blockIdx.x * 64 + tid] = sred[tid];
}

// ---------------- launch ----------------
extern "C" void kernel_launch(void* const* d_in, const int* in_sizes, int n_in,
                              void* d_out, int out_size) {
    const float* node_feat = (const float*)d_in[0];
    const int*   gids0     = (const int*)d_in[1];
    const int*   neigh0    = (const int*)d_in[2];
    const int*   neigh1    = (const int*)d_in[3];
    const float* Ws0       = (const float*)d_in[4];
    const float* Wn0       = (const float*)d_in[5];
    const float* b0        = (const float*)d_in[6];
    const float* Ws1       = (const float*)d_in[7];
    const float* Wn1       = (const float*)d_in[8];
    const float* b1        = (const float*)d_in[9];
    const float* Wp1       = (const float*)d_in[10];
    const float* bp1       = (const float*)d_in[11];
    const float* Wp2       = (const float*)d_in[12];
    const float* bp2       = (const float*)d_in[13];
    const float* Wp3       = (const float*)d_in[14];
    const float* bp3       = (const float*)d_in[15];
    float* out = (float*)d_out;

    float *h0, *h2;
    uint32_t *w0h, *w0l, *w1h, *w1l, *p1h, *p1l, *p2h, *p2l;
    cudaGetSymbolAddress((void**)&h0, g_h0);
    cudaGetSymbolAddress((void**)&h2, g_h2);
    cudaGetSymbolAddress((void**)&w0h, g_W0hi);
    cudaGetSymbolAddress((void**)&w0l, g_W0lo);
    cudaGetSymbolAddress((void**)&w1h, g_W1hi);
    cudaGetSymbolAddress((void**)&w1l, g_W1lo);
    cudaGetSymbolAddress((void**)&p1h, g_P1hi);
    cudaGetSymbolAddress((void**)&p1l, g_P1lo);
    cudaGetSymbolAddress((void**)&p2h, g_P2hi);
    cudaGetSymbolAddress((void**)&p2l, g_P2lo);

    int nsm = 148;
    cudaDeviceGetAttribute(&nsm, cudaDevAttrMultiProcessorCount, 0);

    // smem (u32): L0ws = 4 A buffers + B(hi/lo) + bias + idx
    const int SML0 = (4 * 64 * 132 + 2 * 16 * 264 + 256 + 128 + 2 * 64 * FANC) * 4;  // 175,616
    const int SML1 = (2 * 64 * 132 + 2 * 16 * 264 + 256 + 64 * FANC) * 4;            // 104,192
    const int SMMLP = (2 * 64 * 132 + 2 * 16 * 264 + 3 * 256 + 64) * 4;              // 104,704

    cudaFuncSetAttribute(l0_ws,     cudaFuncAttributeMaxDynamicSharedMemorySize, SML0);
    cudaFuncSetAttribute(l1_gemm,   cudaFuncAttributeMaxDynamicSharedMemorySize, SML1);
    cudaFuncSetAttribute(mlp_fused, cudaFuncAttributeMaxDynamicSharedMemorySize, SMMLP);

    prep_all<<<640, 256>>>(Ws0, Wn0, Ws1, Wn1, Wp1, Wp2,
                           w0h, w0l, w1h, w1l, p1h, p1l, p2h, p2l);

    l0_ws<<<nsm, 512, SML0>>>(node_feat, gids0, neigh0, w0h, w0l, b0, h0);
    l1_gemm<<<N2C / 64, 256, SML1>>>(h0, neigh1, w1h, w1l, b1, h2);
    mlp_fused<<<(2 * NBAT) / 64, 256, SMMLP>>>(h2, p1h, p1l, bp1, p2h, p2l, bp2, Wp3, bp3, out);
}

// round 14
// speedup vs baseline: 1.0467x; 1.0467x over previous
#include <cuda_runtime.h>
#include <cuda_bf16.h>
#include <cstdint>

#define INDIM 128
#define HIDC  256
#define NBAT  4096
#define N2C   12288
#define FANC  10
#define N1C   122880

// ---------------- scratch ----------------
__device__ float    g_h0[(size_t)N1C * HIDC];
__device__ float    g_h2[(size_t)N2C * HIDC];
__device__ uint32_t g_W0hi[128 * 256];   // stacked [Ws0;Wn0], 128 pk rows
__device__ uint32_t g_W0lo[128 * 256];
__device__ uint32_t g_W1hi[256 * 256];   // stacked [Ws1;Wn1], 256 pk rows
__device__ uint32_t g_W1lo[256 * 256];
__device__ uint32_t g_P1hi[128 * 256];
__device__ uint32_t g_P1lo[128 * 256];
__device__ uint32_t g_P2hi[128 * 256];
__device__ uint32_t g_P2lo[128 * 256];

// ---------------- bf16 split helpers ----------------
__device__ __forceinline__ void split_pack(float a, float b, uint32_t& hi, uint32_t& lo) {
    __nv_bfloat16 ha = __float2bfloat16_rn(a);
    __nv_bfloat16 hb = __float2bfloat16_rn(b);
    float la = a - __bfloat162float(ha);
    float lb = b - __bfloat162float(hb);
    __nv_bfloat16 sa = __float2bfloat16_rn(la);
    __nv_bfloat16 sb = __float2bfloat16_rn(lb);
    hi = ((uint32_t)__bfloat16_as_ushort(hb) << 16) | (uint32_t)__bfloat16_as_ushort(ha);
    lo = ((uint32_t)__bfloat16_as_ushort(sb) << 16) | (uint32_t)__bfloat16_as_ushort(sa);
}

__device__ __forceinline__ void store_split4(uint32_t* Ahi, uint32_t* Alo, int idx, float4 v) {
    uint32_t h0, l0, h1, l1;
    split_pack(v.x, v.y, h0, l0);
    split_pack(v.z, v.w, h1, l1);
    *(uint2*)&Ahi[idx] = make_uint2(h0, h1);
    *(uint2*)&Alo[idx] = make_uint2(l0, l1);
}

#define MMA_BF16(c, a, b0v, b1v) \
    asm volatile("mma.sync.aligned.m16n8k16.row.col.f32.bf16.bf16.f32 " \
        "{%0,%1,%2,%3}, {%4,%5,%6,%7}, {%8,%9}, {%0,%1,%2,%3};" \
        : "+f"((c)[0]), "+f"((c)[1]), "+f"((c)[2]), "+f"((c)[3]) \
        : "r"((a)[0]), "r"((a)[1]), "r"((a)[2]), "r"((a)[3]), "r"(b0v), "r"(b1v))

// ---------------- single merged weight pre-split ----------------
__global__ void __launch_bounds__(256)
prep_all(const float* __restrict__ Ws0, const float* __restrict__ Wn0,
         const float* __restrict__ Ws1, const float* __restrict__ Wn1,
         const float* __restrict__ Wp1, const float* __restrict__ Wp2,
         uint32_t* __restrict__ W0hi, uint32_t* __restrict__ W0lo,
         uint32_t* __restrict__ W1hi, uint32_t* __restrict__ W1lo,
         uint32_t* __restrict__ P1hi, uint32_t* __restrict__ P1lo,
         uint32_t* __restrict__ P2hi, uint32_t* __restrict__ P2lo)
{
    int b = blockIdx.x, n = threadIdx.x;
    const float *Wa, *Wb;
    uint32_t *Whi, *Wlo;
    int pk, Ka;
    if (b < 128)      { Wa = Ws0; Wb = Wn0; Whi = W0hi; Wlo = W0lo; pk = b;       Ka = 128; }
    else if (b < 384) { Wa = Ws1; Wb = Wn1; Whi = W1hi; Wlo = W1lo; pk = b - 128; Ka = 256; }
    else if (b < 512) { Wa = Wp1; Wb = Wp1; Whi = P1hi; Wlo = P1lo; pk = b - 384; Ka = 256; }
    else              { Wa = Wp2; Wb = Wp2; Whi = P2hi; Wlo = P2lo; pk = b - 512; Ka = 256; }
    int k0 = 2 * pk, k1 = 2 * pk + 1;
    float f0 = (k0 < Ka) ? __ldg(&Wa[(size_t)k0 * 256 + n]) : __ldg(&Wb[(size_t)(k0 - Ka) * 256 + n]);
    float f1 = (k1 < Ka) ? __ldg(&Wa[(size_t)k1 * 256 + n]) : __ldg(&Wb[(size_t)(k1 - Ka) * 256 + n]);
    uint32_t h, l;
    split_pack(f0, f1, h, l);
    Whi[(size_t)pk * 256 + n] = h;
    Wlo[(size_t)pk * 256 + n] = l;
}

// ---------------- layer0: one-pass fused gather + GEMM (BM=128, 512 threads) ----------------
__global__ void __launch_bounds__(512, 1)
l0_gemm(const float* __restrict__ src,
        const int*   __restrict__ gids,
        const int*   __restrict__ neigh,
        const uint32_t* __restrict__ Whi,
        const uint32_t* __restrict__ Wlo,
        const float* __restrict__ bias,
        float*       __restrict__ out)
{
    constexpr int LDA_U = 132;   // 128 pk + 4 pad
    constexpr int A_U   = 128 * LDA_U;
    constexpr int LDB_U = 264;
    constexpr int B_U   = 16 * LDB_U;

    extern __shared__ uint32_t smem[];
    uint32_t* Ah = smem;
    uint32_t* Al = Ah + A_U;
    uint32_t* Bh = Al + A_U;
    uint32_t* Bl = Bh + B_U;
    float*    bsm = (float*)(Bl + B_U);
    int*      sidx = (int*)(bsm + 256);
    int*      nidx = sidx + 128;

    const int tid  = threadIdx.x;
    const int lane = tid & 31;
    const int wid  = tid >> 5;
    const int wr   = wid >> 2;
    const int wc   = wid & 3;
    const float4* src4 = (const float4*)src;

    if (tid < 256) bsm[tid] = bias[tid];
    if (tid < 128) sidx[tid] = __ldg(&gids[blockIdx.x * 128 + tid]);
    for (int e = tid; e < 128 * FANC; e += 512) {
        int nj = __ldg(&neigh[(size_t)blockIdx.x * 128 * FANC + e]);
        nidx[e] = __ldg(&gids[nj]);
    }
    __syncthreads();

    // ---- gather: rows wid + 16*j, pairs; all loads issued before accumulation ----
    #pragma unroll 1
    for (int g = 0; g < 4; g++) {
        const int r0 = wid + 16 * (2 * g);
        const int r1 = wid + 16 * (2 * g + 1);
        float4 s0 = __ldg(&src4[(size_t)sidx[r0] * 32 + lane]);
        float4 s1 = __ldg(&src4[(size_t)sidx[r1] * 32 + lane]);
        float4 t0[FANC], t1[FANC];
        #pragma unroll
        for (int f = 0; f < FANC; f++) t0[f] = __ldg(&src4[(size_t)nidx[r0 * FANC + f] * 32 + lane]);
        #pragma unroll
        for (int f = 0; f < FANC; f++) t1[f] = __ldg(&src4[(size_t)nidx[r1 * FANC + f] * 32 + lane]);
        float4 a0 = make_float4(0.f, 0.f, 0.f, 0.f);
        float4 a1 = make_float4(0.f, 0.f, 0.f, 0.f);
        #pragma unroll
        for (int f = 0; f < FANC; f++) {
            a0.x += t0[f].x; a0.y += t0[f].y; a0.z += t0[f].z; a0.w += t0[f].w;
            a1.x += t1[f].x; a1.y += t1[f].y; a1.z += t1[f].z; a1.w += t1[f].w;
        }
        store_split4(Ah, Al, r0 * LDA_U + 2 * lane, s0);
        store_split4(Ah, Al, r1 * LDA_U + 2 * lane, s1);
        store_split4(Ah, Al, r0 * LDA_U + 64 + 2 * lane,
                     make_float4(a0.x * 0.1f, a0.y * 0.1f, a0.z * 0.1f, a0.w * 0.1f));
        store_split4(Ah, Al, r1 * LDA_U + 64 + 2 * lane,
                     make_float4(a1.x * 0.1f, a1.y * 0.1f, a1.z * 0.1f, a1.w * 0.1f));
    }

    float acc[2][8][4];
    #pragma unroll
    for (int mt = 0; mt < 2; mt++)
        #pragma unroll
        for (int nt = 0; nt < 8; nt++)
            #pragma unroll
            for (int q = 0; q < 4; q++) acc[mt][nt][q] = 0.f;

    // ---- 8 K-chunks: stage pre-split B (pure copies), MMA ----
    #pragma unroll 1
    for (int c = 0; c < 8; c++) {
        {
            int kp = tid >> 5, off = (tid & 31) * 8;
            const uint4* gh = (const uint4*)(Whi + (size_t)(c * 16 + kp) * 256 + off);
            const uint4* gl = (const uint4*)(Wlo + (size_t)(c * 16 + kp) * 256 + off);
            *(uint4*)&Bh[kp * LDB_U + off]     = __ldg(gh);
            *(uint4*)&Bh[kp * LDB_U + off + 4] = __ldg(gh + 1);
            *(uint4*)&Bl[kp * LDB_U + off]     = __ldg(gl);
            *(uint4*)&Bl[kp * LDB_U + off + 4] = __ldg(gl + 1);
        }
        __syncthreads();

        #pragma unroll
        for (int ks = 0; ks < 2; ks++) {
            const int kpo = c * 16 + ks * 8;
            uint32_t ah[2][4], al[2][4];
            const int ab = (wr * 32 + (lane >> 2)) * LDA_U + (lane & 3) + kpo;
            #pragma unroll
            for (int mt = 0; mt < 2; mt++) {
                int a0i = ab + mt * 16 * LDA_U;
                ah[mt][0] = Ah[a0i];
                ah[mt][1] = Ah[a0i + 8 * LDA_U];
                ah[mt][2] = Ah[a0i + 4];
                ah[mt][3] = Ah[a0i + 8 * LDA_U + 4];
                al[mt][0] = Al[a0i];
                al[mt][1] = Al[a0i + 8 * LDA_U];
                al[mt][2] = Al[a0i + 4];
                al[mt][3] = Al[a0i + 8 * LDA_U + 4];
            }
            const int bb = (ks * 8 + (lane & 3)) * LDB_U + wc * 64 + (lane >> 2);
            #pragma unroll
            for (int nt = 0; nt < 8; nt++) {
                int bi = bb + nt * 8;
                uint32_t bh0 = Bh[bi], bh1 = Bh[bi + 4 * LDB_U];
                uint32_t bl0 = Bl[bi], bl1 = Bl[bi + 4 * LDB_U];
                #pragma unroll
                for (int mt = 0; mt < 2; mt++) {
                    MMA_BF16(acc[mt][nt], ah[mt], bh0, bh1);
                    MMA_BF16(acc[mt][nt], ah[mt], bl0, bl1);
                    MMA_BF16(acc[mt][nt], al[mt], bh0, bh1);
                }
            }
        }
        __syncthreads();
    }

    const int row0 = blockIdx.x * 128 + wr * 32 + (lane >> 2);
    #pragma unroll
    for (int mt = 0; mt < 2; mt++) {
        #pragma unroll
        for (int nt = 0; nt < 8; nt++) {
            int col = wc * 64 + nt * 8 + 2 * (lane & 3);
            float b0 = bsm[col], b1 = bsm[col + 1];
            float v0 = fmaxf(acc[mt][nt][0] + b0, 0.f);
            float v1 = fmaxf(acc[mt][nt][1] + b1, 0.f);
            float v2 = fmaxf(acc[mt][nt][2] + b0, 0.f);
            float v3 = fmaxf(acc[mt][nt][3] + b1, 0.f);
            int r = row0 + mt * 16;
            *(float2*)&out[(size_t)r * HIDC + col]       = make_float2(v0, v1);
            *(float2*)&out[(size_t)(r + 8) * HIDC + col] = make_float2(v2, v3);
        }
    }
}

// ---------------- layer1: two-pass fused (BM=64, 512 threads, 2x8 warp grid) ----------------
__global__ void __launch_bounds__(512, 1)
l1_gemm(const float* __restrict__ src,
        const int*   __restrict__ neigh,
        const uint32_t* __restrict__ Whi,
        const uint32_t* __restrict__ Wlo,
        const float* __restrict__ bias,
        float*       __restrict__ out)
{
    constexpr int LDA_U = 132;
    constexpr int A_U   = 64 * LDA_U;
    constexpr int LDB_U = 264;
    constexpr int B_U   = 16 * LDB_U;

    extern __shared__ uint32_t smem[];
    uint32_t* Ah = smem;
    uint32_t* Al = Ah + A_U;
    uint32_t* Bh = Al + A_U;
    uint32_t* Bl = Bh + B_U;
    float*    bsm = (float*)(Bl + B_U);
    int*      nidx = (int*)(bsm + 256);

    const int tid  = threadIdx.x;
    const int lane = tid & 31;
    const int wid  = tid >> 5;
    const int wr   = wid >> 3;   // 0..1 (32 rows)
    const int wc   = wid & 7;    // 0..7 (32 cols)
    const int base = blockIdx.x * 64;
    const float4* src4 = (const float4*)src;

    if (tid < 256) bsm[tid] = bias[tid];
    for (int e = tid; e < 64 * FANC; e += 512)
        nidx[e] = __ldg(&neigh[(size_t)base * FANC + e]);
    __syncthreads();

    float acc[2][4][4];
    #pragma unroll
    for (int mt = 0; mt < 2; mt++)
        #pragma unroll
        for (int nt = 0; nt < 4; nt++)
            #pragma unroll
            for (int q = 0; q < 4; q++) acc[mt][nt][q] = 0.f;

    #pragma unroll 1
    for (int pass = 0; pass < 2; pass++) {
        if (pass == 0) {
            #pragma unroll
            for (int j = 0; j < 4; j++) {
                int r = wid + 16 * j;
                const float4* p = src4 + (size_t)(base + r) * 64;
                float4 v0 = __ldg(p + lane);
                float4 v1 = __ldg(p + lane + 32);
                store_split4(Ah, Al, r * LDA_U + 2 * lane, v0);
                store_split4(Ah, Al, r * LDA_U + 2 * (lane + 32), v1);
            }
        } else {
            #pragma unroll 1
            for (int j = 0; j < 4; j++) {
                int r = wid + 16 * j;
                float4 t0[FANC], t1[FANC];
                #pragma unroll
                for (int f = 0; f < FANC; f++) {
                    const float4* p = src4 + (size_t)nidx[r * FANC + f] * 64;
                    t0[f] = __ldg(p + lane);
                    t1[f] = __ldg(p + lane + 32);
                }
                float4 a0 = make_float4(0.f, 0.f, 0.f, 0.f);
                float4 a1 = make_float4(0.f, 0.f, 0.f, 0.f);
                #pragma unroll
                for (int f = 0; f < FANC; f++) {
                    a0.x += t0[f].x; a0.y += t0[f].y; a0.z += t0[f].z; a0.w += t0[f].w;
                    a1.x += t1[f].x; a1.y += t1[f].y; a1.z += t1[f].z; a1.w += t1[f].w;
                }
                store_split4(Ah, Al, r * LDA_U + 2 * lane,
                             make_float4(a0.x * 0.1f, a0.y * 0.1f, a0.z * 0.1f, a0.w * 0.1f));
                store_split4(Ah, Al, r * LDA_U + 2 * (lane + 32),
                             make_float4(a1.x * 0.1f, a1.y * 0.1f, a1.z * 0.1f, a1.w * 0.1f));
            }
        }

        #pragma unroll 1
        for (int c = 0; c < 8; c++) {
            {
                int kp = tid >> 5, off = (tid & 31) * 8;
                const uint4* gh = (const uint4*)(Whi + (size_t)(pass * 128 + c * 16 + kp) * 256 + off);
                const uint4* gl = (const uint4*)(Wlo + (size_t)(pass * 128 + c * 16 + kp) * 256 + off);
                *(uint4*)&Bh[kp * LDB_U + off]     = __ldg(gh);
                *(uint4*)&Bh[kp * LDB_U + off + 4] = __ldg(gh + 1);
                *(uint4*)&Bl[kp * LDB_U + off]     = __ldg(gl);
                *(uint4*)&Bl[kp * LDB_U + off + 4] = __ldg(gl + 1);
            }
            __syncthreads();

            #pragma unroll
            for (int ks = 0; ks < 2; ks++) {
                const int kpo = c * 16 + ks * 8;
                uint32_t ah[2][4], al[2][4];
                const int ab = (wr * 32 + (lane >> 2)) * LDA_U + (lane & 3) + kpo;
                #pragma unroll
                for (int mt = 0; mt < 2; mt++) {
                    int a0i = ab + mt * 16 * LDA_U;
                    ah[mt][0] = Ah[a0i];
                    ah[mt][1] = Ah[a0i + 8 * LDA_U];
                    ah[mt][2] = Ah[a0i + 4];
                    ah[mt][3] = Ah[a0i + 8 * LDA_U + 4];
                    al[mt][0] = Al[a0i];
                    al[mt][1] = Al[a0i + 8 * LDA_U];
                    al[mt][2] = Al[a0i + 4];
                    al[mt][3] = Al[a0i + 8 * LDA_U + 4];
                }
                const int bb = (ks * 8 + (lane & 3)) * LDB_U + wc * 32 + (lane >> 2);
                #pragma unroll
                for (int nt = 0; nt < 4; nt++) {
                    int bi = bb + nt * 8;
                    uint32_t bh0 = Bh[bi], bh1 = Bh[bi + 4 * LDB_U];
                    uint32_t bl0 = Bl[bi], bl1 = Bl[bi + 4 * LDB_U];
                    #pragma unroll
                    for (int mt = 0; mt < 2; mt++) {
                        MMA_BF16(acc[mt][nt], ah[mt], bh0, bh1);
                        MMA_BF16(acc[mt][nt], ah[mt], bl0, bl1);
                        MMA_BF16(acc[mt][nt], al[mt], bh0, bh1);
                    }
                }
            }
            __syncthreads();
        }
    }

    const int row0 = base + wr * 32 + (lane >> 2);
    #pragma unroll
    for (int mt = 0; mt < 2; mt++) {
        #pragma unroll
        for (int nt = 0; nt < 4; nt++) {
            int col = wc * 32 + nt * 8 + 2 * (lane & 3);
            float b0 = bsm[col], b1 = bsm[col + 1];
            int r = row0 + mt * 16;
            *(float2*)&out[(size_t)r * HIDC + col] =
                make_float2(acc[mt][nt][0] + b0, acc[mt][nt][1] + b1);
            *(float2*)&out[(size_t)(r + 8) * HIDC + col] =
                make_float2(acc[mt][nt][2] + b0, acc[mt][nt][3] + b1);
        }
    }
}

// ---------------- fused MLP1 + MLP2 + score (512 threads, 2x8 warp grid) ----------------
__global__ void __launch_bounds__(512, 1)
mlp_fused(const float* __restrict__ h2,
          const uint32_t* __restrict__ P1hi, const uint32_t* __restrict__ P1lo,
          const float* __restrict__ bp1,
          const uint32_t* __restrict__ P2hi, const uint32_t* __restrict__ P2lo,
          const float* __restrict__ bp2,
          const float* __restrict__ Wp3, const float* __restrict__ bp3,
          float* __restrict__ out)
{
    constexpr int LDA_U = 132;
    constexpr int A_U   = 64 * LDA_U;
    constexpr int LDB_U = 264;
    constexpr int B_U   = 16 * LDB_U;

    extern __shared__ uint32_t smem[];
    uint32_t* Ahi = smem;
    uint32_t* Alo = Ahi + A_U;
    uint32_t* Bhi = Alo + A_U;
    uint32_t* Blo = Bhi + B_U;
    float* bsm1 = (float*)(Blo + B_U);
    float* bsm2 = bsm1 + 256;
    float* w3   = bsm2 + 256;
    float* sred = w3 + 256;

    const int tid  = threadIdx.x;
    const int lane = tid & 31;
    const int wid  = tid >> 5;
    const int wr   = wid >> 3;   // 0..1
    const int wc   = wid & 7;    // 0..7
    const float4* src4 = (const float4*)h2;

    if (tid < 256) {
        bsm1[tid] = bp1[tid];
        bsm2[tid] = bp2[tid];
        w3[tid]   = Wp3[tid];
    }
    if (tid < 64) sred[tid] = bp3[0];

    for (int r = wid; r < 64; r += 16) {
        int i = blockIdx.x * 64 + r;
        const float4* pa = src4 + (size_t)(i & (NBAT - 1)) * 64;
        const float4* pb = src4 + (size_t)(NBAT + i) * 64;
        #pragma unroll
        for (int h = 0; h < 2; h++) {
            float4 x = __ldg(pa + lane + 32 * h);
            float4 y = __ldg(pb + lane + 32 * h);
            store_split4(Ahi, Alo, r * LDA_U + 2 * (lane + 32 * h),
                         make_float4(x.x * y.x, x.y * y.y, x.z * y.z, x.w * y.w));
        }
    }

    float acc[2][4][4];

    #pragma unroll 1
    for (int layer = 0; layer < 2; layer++) {
        const uint32_t* Wh = (layer == 0) ? P1hi : P2hi;
        const uint32_t* Wl = (layer == 0) ? P1lo : P2lo;

        #pragma unroll
        for (int mt = 0; mt < 2; mt++)
            #pragma unroll
            for (int nt = 0; nt < 4; nt++)
                #pragma unroll
                for (int q = 0; q < 4; q++) acc[mt][nt][q] = 0.f;

        #pragma unroll 1
        for (int c = 0; c < 8; c++) {
            {
                int kp = tid >> 5, off = (tid & 31) * 8;
                const uint4* gh = (const uint4*)(Wh + (size_t)(c * 16 + kp) * 256 + off);
                const uint4* gl = (const uint4*)(Wl + (size_t)(c * 16 + kp) * 256 + off);
                *(uint4*)&Bhi[kp * LDB_U + off]     = __ldg(gh);
                *(uint4*)&Bhi[kp * LDB_U + off + 4] = __ldg(gh + 1);
                *(uint4*)&Blo[kp * LDB_U + off]     = __ldg(gl);
                *(uint4*)&Blo[kp * LDB_U + off + 4] = __ldg(gl + 1);
            }
            __syncthreads();

            #pragma unroll
            for (int ks = 0; ks < 2; ks++) {
                const int kpo = c * 16 + ks * 8;
                uint32_t ah[2][4], al[2][4];
                const int abase = (wr * 32 + (lane >> 2)) * LDA_U + (lane & 3) + kpo;
                #pragma unroll
                for (int mt = 0; mt < 2; mt++) {
                    int a0i = abase + mt * 16 * LDA_U;
                    ah[mt][0] = Ahi[a0i];
                    ah[mt][1] = Ahi[a0i + 8 * LDA_U];
                    ah[mt][2] = Ahi[a0i + 4];
                    ah[mt][3] = Ahi[a0i + 8 * LDA_U + 4];
                    al[mt][0] = Alo[a0i];
                    al[mt][1] = Alo[a0i + 8 * LDA_U];
                    al[mt][2] = Alo[a0i + 4];
                    al[mt][3] = Alo[a0i + 8 * LDA_U + 4];
                }
                const int bbase = (ks * 8 + (lane & 3)) * LDB_U + wc * 32 + (lane >> 2);
                #pragma unroll
                for (int nt = 0; nt < 4; nt++) {
                    int bi = bbase + nt * 8;
                    uint32_t bh0 = Bhi[bi], bh1 = Bhi[bi + 4 * LDB_U];
                    uint32_t bl0 = Blo[bi], bl1 = Blo[bi + 4 * LDB_U];
                    #pragma unroll
                    for (int mt = 0; mt < 2; mt++) {
                        MMA_BF16(acc[mt][nt], ah[mt], bh0, bh1);
                        MMA_BF16(acc[mt][nt], ah[mt], bl0, bl1);
                        MMA_BF16(acc[mt][nt], al[mt], bh0, bh1);
                    }
                }
            }
            __syncthreads();
        }

        if (layer == 0) {
            #pragma unroll
            for (int mt = 0; mt < 2; mt++) {
                int r = wr * 32 + (lane >> 2) + mt * 16;
                #pragma unroll
                for (int nt = 0; nt < 4; nt++) {
                    int col = wc * 32 + nt * 8 + 2 * (lane & 3);
                    float b0 = bsm1[col], b1 = bsm1[col + 1];
                    float v0 = fmaxf(acc[mt][nt][0] + b0, 0.f);
                    float v1 = fmaxf(acc[mt][nt][1] + b1, 0.f);
                    float v2 = fmaxf(acc[mt][nt][2] + b0, 0.f);
                    float v3 = fmaxf(acc[mt][nt][3] + b1, 0.f);
                    uint32_t h, l;
                    split_pack(v0, v1, h, l);
                    Ahi[r * LDA_U + (col >> 1)] = h;
                    Alo[r * LDA_U + (col >> 1)] = l;
                    split_pack(v2, v3, h, l);
                    Ahi[(r + 8) * LDA_U + (col >> 1)] = h;
                    Alo[(r + 8) * LDA_U + (col >> 1)] = l;
                }
            }
            __syncthreads();
        }
    }

    #pragma unroll
    for (int mt = 0; mt < 2; mt++) {
        float sA = 0.f, sB = 0.f;
        #pragma unroll
        for (int nt = 0; nt < 4; nt++) {
            int col = wc * 32 + nt * 8 + 2 * (lane & 3);
            float b0 = bsm2[col], b1 = bsm2[col + 1];
            float w0 = w3[col],  w1 = w3[col + 1];
            sA += fmaxf(acc[mt][nt][0] + b0, 0.f) * w0 + fmaxf(acc[mt][nt][1] + b1, 0.f) * w1;
            sB += fmaxf(acc[mt][nt][2] + b0, 0.f) * w0 + fmaxf(acc[mt][nt][3] + b1, 0.f) * w1;
        }
        sA += __shfl_xor_sync(0xffffffffu, sA, 1);
        sA += __shfl_xor_sync(0xffffffffu, sA, 2);
        sB += __shfl_xor_sync(0xffffffffu, sB, 1);
        sB += __shfl_xor_sync(0xffffffffu, sB, 2);
        if ((lane & 3) == 0) {
            int r = wr * 32 + (lane >> 2) + mt * 16;
            atomicAdd(&sred[r], sA);
            atomicAdd(&sred[r + 8], sB);
        }
    }
    __syncthreads();
    if (tid < 64) out[blockIdx.x * 64 + tid] = sred[tid];
}

// ---------------- launch ----------------
extern "C" void kernel_launch(void* const* d_in, const int* in_sizes, int n_in,
                              void* d_out, int out_size) {
    const float* node_feat = (const float*)d_in[0];
    const int*   gids0     = (const int*)d_in[1];
    const int*   neigh0    = (const int*)d_in[2];
    const int*   neigh1    = (const int*)d_in[3];
    const float* Ws0       = (const float*)d_in[4];
    const float* Wn0       = (const float*)d_in[5];
    const float* b0        = (const float*)d_in[6];
    const float* Ws1       = (const float*)d_in[7];
    const float* Wn1       = (const float*)d_in[8];
    const float* b1        = (const float*)d_in[9];
    const float* Wp1       = (const float*)d_in[10];
    const float* bp1       = (const float*)d_in[11];
    const float* Wp2       = (const float*)d_in[12];
    const float* bp2       = (const float*)d_in[13];
    const float* Wp3       = (const float*)d_in[14];
    const float* bp3       = (const float*)d_in[15];
    float* out = (float*)d_out;

    float *h0, *h2;
    uint32_t *w0h, *w0l, *w1h, *w1l, *p1h, *p1l, *p2h, *p2l;
    cudaGetSymbolAddress((void**)&h0, g_h0);
    cudaGetSymbolAddress((void**)&h2, g_h2);
    cudaGetSymbolAddress((void**)&w0h, g_W0hi);
    cudaGetSymbolAddress((void**)&w0l, g_W0lo);
    cudaGetSymbolAddress((void**)&w1h, g_W1hi);
    cudaGetSymbolAddress((void**)&w1l, g_W1lo);
    cudaGetSymbolAddress((void**)&p1h, g_P1hi);
    cudaGetSymbolAddress((void**)&p1l, g_P1lo);
    cudaGetSymbolAddress((void**)&p2h, g_P2hi);
    cudaGetSymbolAddress((void**)&p2l, g_P2lo);

    // smem (u32)
    const int SML0 = (2 * 128 * 132 + 2 * 16 * 264 + 256 + 128 + 128 * FANC) * 4;  // 175,616
    const int SML1 = (2 * 64 * 132 + 2 * 16 * 264 + 256 + 64 * FANC) * 4;          // 104,192
    const int SMMLP = (2 * 64 * 132 + 2 * 16 * 264 + 3 * 256 + 64) * 4;            // 104,704

    cudaFuncSetAttribute(l0_gemm,   cudaFuncAttributeMaxDynamicSharedMemorySize, SML0);
    cudaFuncSetAttribute(l1_gemm,   cudaFuncAttributeMaxDynamicSharedMemorySize, SML1);
    cudaFuncSetAttribute(mlp_fused, cudaFuncAttributeMaxDynamicSharedMemorySize, SMMLP);

    prep_all<<<640, 256>>>(Ws0, Wn0, Ws1, Wn1, Wp1, Wp2,
                           w0h, w0l, w1h, w1l, p1h, p1l, p2h, p2l);

    l0_gemm<<<N1C / 128, 512, SML0>>>(node_feat, gids0, neigh0, w0h, w0l, b0, h0);
    l1_gemm<<<N2C / 64, 512, SML1>>>(h0, neigh1, w1h, w1l, b1, h2);
    mlp_fused<<<(2 * NBAT) / 64, 512, SMMLP>>>(h2, p1h, p1l, bp1, p2h, p2l, bp2, Wp3, bp3, out);
}